// round 16
// baseline (speedup 1.0000x reference)
#include <cuda_runtime.h>
#include <cuda_fp16.h>
#include <cstdint>
#include <cstddef>

// Problem constants
#define E_DIM   256
#define FF_DIM  1024
#define H_HEADS 8
#define D_HEAD  32
#define NH      8
#define B_SZ    2
#define N_SEQ   8192
#define M_ROWS  (B_SZ * N_SEQ * NH)      // 131072
#define BN_TOK  (B_SZ * N_SEQ)           // 16384

// Scratch (device globals: allocation-free rule)
__device__ __half g_hx  [(size_t)M_ROWS * E_DIM];
__device__ __half g_ht  [(size_t)M_ROWS * E_DIM];
__device__ __half g_hqkv[(size_t)3 * M_ROWS * E_DIM];   // q|k|v contiguous
__device__ __half g_ha  [(size_t)M_ROWS * E_DIM];
__device__ __half g_hh1 [(size_t)M_ROWS * E_DIM];
__device__ __half g_hff [(size_t)M_ROWS * FF_DIM];
__device__ float  g_ft  [(size_t)M_ROWS * E_DIM];   // t (fp32 residual)
__device__ float  g_fh1 [(size_t)M_ROWS * E_DIM];   // h1 (fp32 residual)

// Transposed fp16 weights [N][K]
__device__ __half g_wt_in [E_DIM * E_DIM];
__device__ __half g_wt_qkv[3 * E_DIM * E_DIM];
__device__ __half g_wt_o  [E_DIM * E_DIM];
__device__ __half g_wt_f1 [E_DIM * FF_DIM];
__device__ __half g_wt_f2 [FF_DIM * E_DIM];
__device__ float  g_bqkv  [3 * E_DIM];

__device__ __forceinline__ uint32_t smem_u32(const void* p) {
    return (uint32_t)__cvta_generic_to_shared(p);
}

// ---------------------------------------------------------------------------
// Weight transpose + fp16 round: Wt[n][k] = h(W[k][n])
// ---------------------------------------------------------------------------
__global__ __launch_bounds__(256)
void transpose_kernel(const float* __restrict__ W, __half* __restrict__ Wt, int K, int N)
{
    int idx = blockIdx.x * 256 + threadIdx.x;
    if (idx >= K * N) return;
    int k = idx / N, n = idx - k * N;
    Wt[(size_t)n * K + k] = __float2half_rn(W[idx]);
}

__global__ __launch_bounds__(256)
void concat_bias_kernel(const float* __restrict__ a, const float* __restrict__ b,
                        const float* __restrict__ c, float* __restrict__ o)
{
    int i = blockIdx.x * 256 + threadIdx.x;
    if (i < 256)       o[i] = a[i];
    else if (i < 512)  o[i] = b[i - 256];
    else if (i < 768)  o[i] = c[i - 512];
}

__global__ __launch_bounds__(256)
void conv_kernel(const float* __restrict__ in, __half* __restrict__ out, size_t n8)
{
    size_t i = (size_t)blockIdx.x * 256 + threadIdx.x;
    if (i >= n8) return;
    float4 a = ((const float4*)in)[i * 2 + 0];
    float4 b = ((const float4*)in)[i * 2 + 1];
    __half2 h0 = __floats2half2_rn(a.x, a.y);
    __half2 h1 = __floats2half2_rn(a.z, a.w);
    __half2 h2 = __floats2half2_rn(b.x, b.y);
    __half2 h3 = __floats2half2_rn(b.z, b.w);
    uint4 o = { *(uint32_t*)&h0, *(uint32_t*)&h1, *(uint32_t*)&h2, *(uint32_t*)&h3 };
    ((uint4*)out)[i] = o;
}

// ---------------------------------------------------------------------------
// FP16 TC GEMM, CTA tile 128x256x64, 512 thr (16 warps, warp tile 64x32),
// cp.async 2-stage. Optional fused epilogues:
//   act=1: silu ; ln=1: row LayerNorm over N=256 (+optional residual)
//   qkv=1: N=768 split into 3 [M][256] buffers
// LN stats: atomic-free two-stage reduction in dedicated static shared mem.
// ---------------------------------------------------------------------------
#define BKH    64
#define SPITCH 72                          // halves per smem row (144B)
#define A_STG  (128 * SPITCH)              // halves
#define B_STG  (256 * SPITCH)
#define STG    (A_STG + B_STG)
#define GEMM_SMEM (2 * STG * 2)            // bytes = 110592

__device__ __forceinline__ void load_stage(const __half* __restrict__ A,
                                           const __half* __restrict__ Wt,
                                           size_t bm, size_t bn, int K, int k0,
                                           __half* Abuf, __half* Bbuf, int tid)
{
#pragma unroll
    for (int i = 0; i < 2; i++) {
        int idx = i * 512 + tid;
        int row = idx >> 3;
        int c   = idx & 7;
        uint32_t dst = smem_u32(&Abuf[row * SPITCH + c * 8]);
        const __half* src = A + (bm + row) * (size_t)K + k0 + c * 8;
        asm volatile("cp.async.cg.shared.global [%0], [%1], 16;" :: "r"(dst), "l"(src));
    }
#pragma unroll
    for (int i = 0; i < 4; i++) {
        int idx = i * 512 + tid;
        int row = idx >> 3;
        int c   = idx & 7;
        uint32_t dst = smem_u32(&Bbuf[row * SPITCH + c * 8]);
        const __half* src = Wt + (bn + row) * (size_t)K + k0 + c * 8;
        asm volatile("cp.async.cg.shared.global [%0], [%1], 16;" :: "r"(dst), "l"(src));
    }
}

__global__ __launch_bounds__(512, 1)
void gemm_h(const __half* __restrict__ A, const __half* __restrict__ Wt,
            const float* __restrict__ bias, const float* __restrict__ resid,
            const float* __restrict__ gamma, const float* __restrict__ beta,
            __half* __restrict__ Ch, float* __restrict__ Cf,
            int K, int N, int act, int qkv, int ln)
{
    extern __shared__ __half smem[];
    __half* Abuf[2] = { smem,         smem + STG };
    __half* Bbuf[2] = { smem + A_STG, smem + STG + A_STG };

    // Dedicated static shared for LN stats (no aliasing of pipeline buffers)
    __shared__ float spart1[8][128];
    __shared__ float spart2[8][128];
    __shared__ float smean[128];
    __shared__ float sinv[128];

    const int tid  = threadIdx.x;
    const int lane = tid & 31;
    const int warp = tid >> 5;
    const int wm   = (warp & 1) * 64;
    const int wn   = (warp >> 1) * 32;
    const int wg   = warp >> 1;            // column-slice id (0..7)
    const int g    = lane >> 2;
    const int tig  = lane & 3;
    const int r8   = lane & 7;
    const int quad = lane >> 3;

    const size_t bm = (size_t)blockIdx.y * 128;
    const size_t bn = (size_t)blockIdx.x * 256;
    const int KT = K / BKH;

    float acc[4][4][4];
#pragma unroll
    for (int mt = 0; mt < 4; mt++)
#pragma unroll
        for (int nt = 0; nt < 4; nt++)
#pragma unroll
            for (int i = 0; i < 4; i++) acc[mt][nt][i] = 0.f;

    load_stage(A, Wt, bm, bn, K, 0, Abuf[0], Bbuf[0], tid);
    asm volatile("cp.async.commit_group;" ::: "memory");

    for (int kt = 0; kt < KT; kt++) {
        const int c = kt & 1;
        __syncthreads();
        if (kt + 1 < KT) {
            load_stage(A, Wt, bm, bn, K, (kt + 1) * BKH, Abuf[c ^ 1], Bbuf[c ^ 1], tid);
            asm volatile("cp.async.commit_group;" ::: "memory");
            asm volatile("cp.async.wait_group 1;" ::: "memory");
        } else {
            asm volatile("cp.async.wait_group 0;" ::: "memory");
        }
        __syncthreads();

        const __half* As = Abuf[c];
        const __half* Bs = Bbuf[c];
#pragma unroll
        for (int kk = 0; kk < 4; kk++) {
            const int kb = kk * 16;

            uint32_t af[4][4];
#pragma unroll
            for (int mt = 0; mt < 4; mt++) {
                int row = wm + mt * 16 + (quad & 1) * 8 + r8;
                int col = kb + (quad >> 1) * 8;
                uint32_t addr = smem_u32(&As[row * SPITCH + col]);
                asm volatile(
                    "ldmatrix.sync.aligned.m8n8.x4.shared.b16 {%0,%1,%2,%3}, [%4];"
                    : "=r"(af[mt][0]), "=r"(af[mt][1]), "=r"(af[mt][2]), "=r"(af[mt][3])
                    : "r"(addr));
            }

            uint32_t bf[4][2];
#pragma unroll
            for (int p = 0; p < 2; p++) {
                int row = wn + p * 16 + (quad >> 1) * 8 + r8;
                int col = kb + (quad & 1) * 8;
                uint32_t addr = smem_u32(&Bs[row * SPITCH + col]);
                uint32_t t0, t1, t2, t3;
                asm volatile(
                    "ldmatrix.sync.aligned.m8n8.x4.shared.b16 {%0,%1,%2,%3}, [%4];"
                    : "=r"(t0), "=r"(t1), "=r"(t2), "=r"(t3)
                    : "r"(addr));
                bf[2 * p + 0][0] = t0; bf[2 * p + 0][1] = t1;
                bf[2 * p + 1][0] = t2; bf[2 * p + 1][1] = t3;
            }

#pragma unroll
            for (int mt = 0; mt < 4; mt++)
#pragma unroll
                for (int nt = 0; nt < 4; nt++) {
                    asm volatile(
                        "mma.sync.aligned.m16n8k16.row.col.f32.f16.f16.f32 "
                        "{%0,%1,%2,%3}, {%4,%5,%6,%7}, {%8,%9}, {%0,%1,%2,%3};"
                        : "+f"(acc[mt][nt][0]), "+f"(acc[mt][nt][1]),
                          "+f"(acc[mt][nt][2]), "+f"(acc[mt][nt][3])
                        : "r"(af[mt][0]), "r"(af[mt][1]), "r"(af[mt][2]), "r"(af[mt][3]),
                          "r"(bf[nt][0]), "r"(bf[nt][1]));
                }
        }
    }

    // -------------------- Epilogue --------------------
    // Bias / residual / silu folded into acc.
#pragma unroll
    for (int mt = 0; mt < 4; mt++) {
#pragma unroll
        for (int nt = 0; nt < 4; nt++) {
            int cloc = wn + nt * 8 + tig * 2;
            float b0 = 0.f, b1 = 0.f;
            if (bias) { b0 = bias[bn + cloc]; b1 = bias[bn + cloc + 1]; }
            acc[mt][nt][0] += b0; acc[mt][nt][1] += b1;
            acc[mt][nt][2] += b0; acc[mt][nt][3] += b1;
            if (resid) {
                size_t row0 = bm + wm + mt * 16 + g;
                float2 r01 = *(const float2*)&resid[row0 * 256 + cloc];
                float2 r23 = *(const float2*)&resid[(row0 + 8) * 256 + cloc];
                acc[mt][nt][0] += r01.x; acc[mt][nt][1] += r01.y;
                acc[mt][nt][2] += r23.x; acc[mt][nt][3] += r23.y;
            }
            if (act == 1) {
#pragma unroll
                for (int i = 0; i < 4; i++) {
                    float v = acc[mt][nt][i];
                    acc[mt][nt][i] = v / (1.f + expf(-v));
                }
            }
        }
    }

    float rmean[4][2], rinv[4][2];
    if (ln) {
        // Stage 1: each warp owns a disjoint 32-column slice (wg) and writes
        // per-row partial sums. Unique (wg,row) cells -> no atomics needed.
#pragma unroll
        for (int mt = 0; mt < 4; mt++) {
            float p0 = 0.f, q0 = 0.f, p1 = 0.f, q1 = 0.f;
#pragma unroll
            for (int nt = 0; nt < 4; nt++) {
                p0 += acc[mt][nt][0] + acc[mt][nt][1];
                q0 += acc[mt][nt][0] * acc[mt][nt][0] + acc[mt][nt][1] * acc[mt][nt][1];
                p1 += acc[mt][nt][2] + acc[mt][nt][3];
                q1 += acc[mt][nt][2] * acc[mt][nt][2] + acc[mt][nt][3] * acc[mt][nt][3];
            }
#pragma unroll
            for (int o = 1; o <= 2; o <<= 1) {
                p0 += __shfl_xor_sync(0xffffffffu, p0, o);
                q0 += __shfl_xor_sync(0xffffffffu, q0, o);
                p1 += __shfl_xor_sync(0xffffffffu, p1, o);
                q1 += __shfl_xor_sync(0xffffffffu, q1, o);
            }
            if (tig == 0) {
                int r0 = wm + mt * 16 + g;
                spart1[wg][r0] = p0;     spart2[wg][r0] = q0;
                spart1[wg][r0 + 8] = p1; spart2[wg][r0 + 8] = q1;
            }
        }
        __syncthreads();

        // Stage 2: 128 threads fold the 8 slice-partials per row.
        if (tid < 128) {
            float s = 0.f, s2 = 0.f;
#pragma unroll
            for (int w = 0; w < 8; w++) { s += spart1[w][tid]; s2 += spart2[w][tid]; }
            float m  = s * (1.f / 256.f);
            float vv = s2 * (1.f / 256.f) - m * m;
            smean[tid] = m;
            sinv[tid]  = rsqrtf(vv + 1e-5f);
        }
        __syncthreads();

#pragma unroll
        for (int mt = 0; mt < 4; mt++) {
            int r0 = wm + mt * 16 + g;
#pragma unroll
            for (int hh = 0; hh < 2; hh++) {
                rmean[mt][hh] = smean[r0 + hh * 8];
                rinv[mt][hh]  = sinv[r0 + hh * 8];
            }
        }
    }

    // Output target
    __half* chp = Ch;
    float*  cfp = Cf;
    int n_stride = N;
    size_t col_base = bn;
    if (qkv) {
        chp = Ch + (size_t)blockIdx.x * ((size_t)M_ROWS * E_DIM);
        n_stride = E_DIM;
        col_base = 0;
    }

#pragma unroll
    for (int mt = 0; mt < 4; mt++) {
#pragma unroll
        for (int nt = 0; nt < 4; nt++) {
            size_t row0 = bm + wm + mt * 16 + g;
            int    cloc = wn + nt * 8 + tig * 2;
            size_t col  = col_base + cloc;
            float v0 = acc[mt][nt][0], v1 = acc[mt][nt][1];
            float v2 = acc[mt][nt][2], v3 = acc[mt][nt][3];
            if (ln) {
                float ga0 = gamma[cloc], ga1 = gamma[cloc + 1];
                float be0 = beta[cloc],  be1 = beta[cloc + 1];
                v0 = (v0 - rmean[mt][0]) * rinv[mt][0] * ga0 + be0;
                v1 = (v1 - rmean[mt][0]) * rinv[mt][0] * ga1 + be1;
                v2 = (v2 - rmean[mt][1]) * rinv[mt][1] * ga0 + be0;
                v3 = (v3 - rmean[mt][1]) * rinv[mt][1] * ga1 + be1;
            }
            if (cfp) {
                float2 o01 = { v0, v1 };
                float2 o23 = { v2, v3 };
                *(float2*)&cfp[row0 * n_stride + col]       = o01;
                *(float2*)&cfp[(row0 + 8) * n_stride + col] = o23;
            }
            if (chp) {
                __half2 h01 = __floats2half2_rn(v0, v1);
                __half2 h23 = __floats2half2_rn(v2, v3);
                *(__half2*)&chp[row0 * n_stride + col]       = h01;
                *(__half2*)&chp[(row0 + 8) * n_stride + col] = h23;
            }
        }
    }
}

// ---------------------------------------------------------------------------
// Attention: per-token attention over NH=8 positions, H=8 heads, d=32.
// ---------------------------------------------------------------------------
__global__ __launch_bounds__(256)
void attn_kernel(const __half* __restrict__ qkv,
                 const float* __restrict__ pos1, const float* __restrict__ pos2,
                 const float* __restrict__ W_pos, const float* __restrict__ W_bias,
                 __half* __restrict__ out)
{
    const size_t QKV_OFF = (size_t)M_ROWS * E_DIM;
    const __half* q = qkv;
    const __half* k = qkv + QKV_OFF;
    const __half* v = qkv + 2 * QKV_OFF;

    int bn  = blockIdx.x;
    int tid = threadIdx.x;
    size_t base = (size_t)bn * NH * E_DIM;

    __shared__ __half sq[NH][E_DIM];
    __shared__ __half sk[NH][E_DIM];
    __shared__ __half sv[NH][E_DIM];
    __shared__ float  sbias[NH][H_HEADS];
    __shared__ float  satt[H_HEADS][NH][NH];

    {
        int r  = tid >> 5;
        int c8 = (tid & 31) * 8;
        *(uint4*)&sq[r][c8] = *(const uint4*)&q[base + (size_t)r * E_DIM + c8];
        *(uint4*)&sk[r][c8] = *(const uint4*)&k[base + (size_t)r * E_DIM + c8];
        *(uint4*)&sv[r][c8] = *(const uint4*)&v[base + (size_t)r * E_DIM + c8];
    }

    if (tid < NH * H_HEADS) {
        int nh = tid >> 3;
        int h  = tid & 7;
        size_t pbase = ((size_t)bn * NH + nh) * 2;
        float p0 = pos1[pbase + 0], p1 = pos1[pbase + 1];
        float p2 = pos2[pbase + 0], p3 = pos2[pbase + 1];
        float acc = 0.f;
#pragma unroll
        for (int pe = 0; pe < 32; pe++) {
            float e = p0 * W_pos[0 * 32 + pe] + p1 * W_pos[1 * 32 + pe]
                    + p2 * W_pos[2 * 32 + pe] + p3 * W_pos[3 * 32 + pe];
            e = e / (1.f + expf(-e));
            acc += e * W_bias[pe * H_HEADS + h];
        }
        sbias[nh][h] = acc;
    }
    __syncthreads();

    const float scale = 0.17677669529663687f;  // 1/sqrt(32)
#pragma unroll
    for (int it = 0; it < 2; it++) {
        int idx = tid + it * 256;
        int h  = idx >> 6;
        int qi = (idx >> 3) & 7;
        int ki = idx & 7;
        const __half2* qp = (const __half2*)&sq[qi][h * D_HEAD];
        const __half2* kp = (const __half2*)&sk[ki][h * D_HEAD];
        float s = 0.f;
#pragma unroll
        for (int j = 0; j < 16; j++) {
            float2 aq = __half22float2(qp[j]);
            float2 ak = __half22float2(kp[j]);
            s += aq.x * ak.x + aq.y * ak.y;
        }
        satt[h][qi][ki] = s * scale + sbias[ki][h];
    }
    __syncthreads();

    if (tid < H_HEADS * NH) {
        int h  = tid >> 3;
        int qi = tid & 7;
        float mx = satt[h][qi][0];
#pragma unroll
        for (int ki = 1; ki < NH; ki++) mx = fmaxf(mx, satt[h][qi][ki]);
        float sum = 0.f;
        float ex[NH];
#pragma unroll
        for (int ki = 0; ki < NH; ki++) { ex[ki] = expf(satt[h][qi][ki] - mx); sum += ex[ki]; }
        float rs = 1.f / sum;
#pragma unroll
        for (int ki = 0; ki < NH; ki++) satt[h][qi][ki] = ex[ki] * rs;
    }
    __syncthreads();

#pragma unroll
    for (int it = 0; it < 4; it++) {
        int idx = it * 256 + tid;
        int qi  = idx >> 7;
        int c2  = idx & 127;
        int h   = c2 >> 4;
        float2 o = { 0.f, 0.f };
        const float* att = &satt[h][qi][0];
#pragma unroll
        for (int ki = 0; ki < NH; ki++) {
            float2 vv = __half22float2(((const __half2*)&sv[ki][0])[c2]);
            o.x += att[ki] * vv.x;
            o.y += att[ki] * vv.y;
        }
        *(__half2*)&out[base + (size_t)qi * E_DIM + c2 * 2] = __floats2half2_rn(o.x, o.y);
    }
}

// ---------------------------------------------------------------------------
// Host launcher
// ---------------------------------------------------------------------------
extern "C" void kernel_launch(void* const* d_in, const int* in_sizes, int n_in,
                              void* d_out, int out_size)
{
    const float* x     = (const float*)d_in[0];
    const float* pos1  = (const float*)d_in[1];
    const float* pos2  = (const float*)d_in[2];
    const float* W_in  = (const float*)d_in[3];
    const float* gin   = (const float*)d_in[4];
    const float* bin   = (const float*)d_in[5];
    const float* Wq    = (const float*)d_in[6];
    const float* bq    = (const float*)d_in[7];
    const float* Wk    = (const float*)d_in[8];
    const float* bk    = (const float*)d_in[9];
    const float* Wv    = (const float*)d_in[10];
    const float* bv    = (const float*)d_in[11];
    const float* Wo    = (const float*)d_in[12];
    const float* bo    = (const float*)d_in[13];
    const float* W_pos = (const float*)d_in[14];
    const float* W_bias= (const float*)d_in[15];
    const float* W_ff1 = (const float*)d_in[16];
    const float* W_ff2 = (const float*)d_in[17];
    const float* g1    = (const float*)d_in[18];
    const float* b1    = (const float*)d_in[19];
    const float* g2    = (const float*)d_in[20];
    const float* b2    = (const float*)d_in[21];

    __half *hx, *ht, *hqkv, *ha, *hh1, *hff;
    float  *ft, *fh1, *bqkv;
    __half *wt_in, *wt_qkv, *wt_o, *wt_f1, *wt_f2;
    cudaGetSymbolAddress((void**)&hx,   g_hx);
    cudaGetSymbolAddress((void**)&ht,   g_ht);
    cudaGetSymbolAddress((void**)&hqkv, g_hqkv);
    cudaGetSymbolAddress((void**)&ha,   g_ha);
    cudaGetSymbolAddress((void**)&hh1,  g_hh1);
    cudaGetSymbolAddress((void**)&hff,  g_hff);
    cudaGetSymbolAddress((void**)&ft,   g_ft);
    cudaGetSymbolAddress((void**)&fh1,  g_fh1);
    cudaGetSymbolAddress((void**)&bqkv,  g_bqkv);
    cudaGetSymbolAddress((void**)&wt_in, g_wt_in);
    cudaGetSymbolAddress((void**)&wt_qkv,g_wt_qkv);
    cudaGetSymbolAddress((void**)&wt_o,  g_wt_o);
    cudaGetSymbolAddress((void**)&wt_f1, g_wt_f1);
    cudaGetSymbolAddress((void**)&wt_f2, g_wt_f2);

    cudaFuncSetAttribute(gemm_h, cudaFuncAttributeMaxDynamicSharedMemorySize, GEMM_SMEM);

    int nEE = E_DIM * E_DIM, nEF = E_DIM * FF_DIM;
    transpose_kernel<<<(nEE + 255) / 256, 256>>>(W_in,  wt_in,            E_DIM, E_DIM);
    transpose_kernel<<<(nEE + 255) / 256, 256>>>(Wq,    wt_qkv,           E_DIM, E_DIM);
    transpose_kernel<<<(nEE + 255) / 256, 256>>>(Wk,    wt_qkv + 1 * nEE, E_DIM, E_DIM);
    transpose_kernel<<<(nEE + 255) / 256, 256>>>(Wv,    wt_qkv + 2 * nEE, E_DIM, E_DIM);
    transpose_kernel<<<(nEE + 255) / 256, 256>>>(Wo,    wt_o,             E_DIM, E_DIM);
    transpose_kernel<<<(nEF + 255) / 256, 256>>>(W_ff1, wt_f1,            E_DIM, FF_DIM);
    transpose_kernel<<<(nEF + 255) / 256, 256>>>(W_ff2, wt_f2,            FF_DIM, E_DIM);
    concat_bias_kernel<<<3, 256>>>(bq, bk, bv, bqkv);

    size_t x8 = (size_t)M_ROWS * E_DIM / 8;
    conv_kernel<<<(unsigned)((x8 + 255) / 256), 256>>>(x, hx, x8);

    dim3 blk(512);
    dim3 gE  (1, M_ROWS / 128);    // N=256
    dim3 gQKV(3, M_ROWS / 128);    // N=768
    dim3 gFF (4, M_ROWS / 128);    // N=1024

    // 1. t = LN(x @ W_in) -> ht (fp16) + ft (fp32)     [fused LN]
    gemm_h<<<gE, blk, GEMM_SMEM>>>(hx, wt_in, nullptr, nullptr, gin, bin,
                                   ht, ft, E_DIM, E_DIM, 0, 0, 1);

    // 2. fused q|k|v projection -> hqkv
    gemm_h<<<gQKV, blk, GEMM_SMEM>>>(ht, wt_qkv, bqkv, nullptr, nullptr, nullptr,
                                     hqkv, nullptr, E_DIM, 3 * E_DIM, 0, 1, 0);

    // 3. attention (+positional bias) -> ha
    attn_kernel<<<BN_TOK, 256>>>(hqkv, pos1, pos2, W_pos, W_bias, ha);

    // 4+5. h1 = LN(t + attn@Wo + bo) -> hh1 (fp16) + fh1 (fp32)   [fused]
    gemm_h<<<gE, blk, GEMM_SMEM>>>(ha, wt_o, bo, ft, g1, b1,
                                   hh1, fh1, E_DIM, E_DIM, 0, 0, 1);

    // 6. ff = silu(h1 @ W_ff1) -> hff
    gemm_h<<<gFF, blk, GEMM_SMEM>>>(hh1, wt_f1, nullptr, nullptr, nullptr, nullptr,
                                    hff, nullptr, E_DIM, FF_DIM, 1, 0, 0);

    // 7+8. out = LN(h1 + ff @ W_ff2) -> d_out (fp32)   [fused]
    gemm_h<<<gE, blk, GEMM_SMEM>>>(hff, wt_f2, nullptr, fh1, g2, b2,
                                   nullptr, (float*)d_out, FF_DIM, E_DIM, 0, 0, 1);
}

// round 17
// speedup vs baseline: 1.0588x; 1.0588x over previous
#include <cuda_runtime.h>
#include <cuda_fp16.h>
#include <cstdint>
#include <cstddef>

// Problem constants
#define E_DIM   256
#define FF_DIM  1024
#define H_HEADS 8
#define D_HEAD  32
#define NH      8
#define B_SZ    2
#define N_SEQ   8192
#define M_ROWS  (B_SZ * N_SEQ * NH)      // 131072
#define BN_TOK  (B_SZ * N_SEQ)           // 16384

// Scratch (device globals: allocation-free rule)
__device__ __half g_hx  [(size_t)M_ROWS * E_DIM];
__device__ __half g_ht  [(size_t)M_ROWS * E_DIM];
__device__ __half g_hqkv[(size_t)3 * M_ROWS * E_DIM];   // q|k|v contiguous
__device__ __half g_ha  [(size_t)M_ROWS * E_DIM];
__device__ __half g_hh1 [(size_t)M_ROWS * E_DIM];
__device__ __half g_hff [(size_t)M_ROWS * FF_DIM];
__device__ float  g_ft  [(size_t)M_ROWS * E_DIM];   // t (fp32 residual)
__device__ float  g_fh1 [(size_t)M_ROWS * E_DIM];   // h1 (fp32 residual)

// Transposed fp16 weights [N][K]
__device__ __half g_wt_in [E_DIM * E_DIM];
__device__ __half g_wt_qkv[3 * E_DIM * E_DIM];
__device__ __half g_wt_o  [E_DIM * E_DIM];
__device__ __half g_wt_f1 [E_DIM * FF_DIM];
__device__ __half g_wt_f2 [FF_DIM * E_DIM];
__device__ float  g_bqkv  [3 * E_DIM];

__device__ __forceinline__ uint32_t smem_u32(const void* p) {
    return (uint32_t)__cvta_generic_to_shared(p);
}

// ---------------------------------------------------------------------------
// Weight transpose + fp16 round: Wt[n][k] = h(W[k][n])
// ---------------------------------------------------------------------------
__global__ __launch_bounds__(256)
void transpose_kernel(const float* __restrict__ W, __half* __restrict__ Wt, int K, int N)
{
    int idx = blockIdx.x * 256 + threadIdx.x;
    if (idx >= K * N) return;
    int k = idx / N, n = idx - k * N;
    Wt[(size_t)n * K + k] = __float2half_rn(W[idx]);
}

__global__ __launch_bounds__(256)
void concat_bias_kernel(const float* __restrict__ a, const float* __restrict__ b,
                        const float* __restrict__ c, float* __restrict__ o)
{
    int i = blockIdx.x * 256 + threadIdx.x;
    if (i < 256)       o[i] = a[i];
    else if (i < 512)  o[i] = b[i - 256];
    else if (i < 768)  o[i] = c[i - 512];
}

__global__ __launch_bounds__(256)
void conv_kernel(const float* __restrict__ in, __half* __restrict__ out, size_t n8)
{
    size_t i = (size_t)blockIdx.x * 256 + threadIdx.x;
    if (i >= n8) return;
    float4 a = ((const float4*)in)[i * 2 + 0];
    float4 b = ((const float4*)in)[i * 2 + 1];
    __half2 h0 = __floats2half2_rn(a.x, a.y);
    __half2 h1 = __floats2half2_rn(a.z, a.w);
    __half2 h2 = __floats2half2_rn(b.x, b.y);
    __half2 h3 = __floats2half2_rn(b.z, b.w);
    uint4 o = { *(uint32_t*)&h0, *(uint32_t*)&h1, *(uint32_t*)&h2, *(uint32_t*)&h3 };
    ((uint4*)out)[i] = o;
}

// ---------------------------------------------------------------------------
// FP16 TC GEMM, CTA tile 64x256x64, 256 thr (8 warps: 2x4 grid of 32x64
// warp tiles), cp.async 2-stage, 2 CTAs/SM. Fused epilogues:
//   act=1: silu ; ln=1: row LayerNorm over N=256 (+optional residual)
//   qkv=1: N=768 split into 3 [M][256] buffers
// ---------------------------------------------------------------------------
#define BKH    64
#define SPITCH 72                          // halves per smem row (144B)
#define A_STG  (64 * SPITCH)               // halves
#define B_STG  (256 * SPITCH)
#define STG    (A_STG + B_STG)
#define GEMM_SMEM (2 * STG * 2)            // bytes = 92160

__device__ __forceinline__ void load_stage(const __half* __restrict__ A,
                                           const __half* __restrict__ Wt,
                                           size_t bm, size_t bn, int K, int k0,
                                           __half* Abuf, __half* Bbuf, int tid)
{
#pragma unroll
    for (int i = 0; i < 2; i++) {
        int idx = i * 256 + tid;
        int row = idx >> 3;
        int c   = idx & 7;
        uint32_t dst = smem_u32(&Abuf[row * SPITCH + c * 8]);
        const __half* src = A + (bm + row) * (size_t)K + k0 + c * 8;
        asm volatile("cp.async.cg.shared.global [%0], [%1], 16;" :: "r"(dst), "l"(src));
    }
#pragma unroll
    for (int i = 0; i < 8; i++) {
        int idx = i * 256 + tid;
        int row = idx >> 3;
        int c   = idx & 7;
        uint32_t dst = smem_u32(&Bbuf[row * SPITCH + c * 8]);
        const __half* src = Wt + (bn + row) * (size_t)K + k0 + c * 8;
        asm volatile("cp.async.cg.shared.global [%0], [%1], 16;" :: "r"(dst), "l"(src));
    }
}

__global__ __launch_bounds__(256, 2)
void gemm_h(const __half* __restrict__ A, const __half* __restrict__ Wt,
            const float* __restrict__ bias, const float* __restrict__ resid,
            const float* __restrict__ gamma, const float* __restrict__ beta,
            __half* __restrict__ Ch, float* __restrict__ Cf,
            int K, int N, int act, int qkv, int ln)
{
    extern __shared__ __half smem[];
    __half* Abuf[2] = { smem,         smem + STG };
    __half* Bbuf[2] = { smem + A_STG, smem + STG + A_STG };

    // Dedicated static shared for LN stats (atomic-free two-stage reduction)
    __shared__ float spart1[4][64];
    __shared__ float spart2[4][64];
    __shared__ float smean[64];
    __shared__ float sinv[64];

    const int tid  = threadIdx.x;
    const int lane = tid & 31;
    const int warp = tid >> 5;
    const int wm   = (warp & 1) * 32;      // 2 m-warps of 32 rows
    const int wn   = (warp >> 1) * 64;     // 4 n-warps of 64 cols
    const int wg   = warp >> 1;            // column-slice id (0..3)
    const int g    = lane >> 2;
    const int tig  = lane & 3;
    const int r8   = lane & 7;
    const int quad = lane >> 3;

    const size_t bm = (size_t)blockIdx.y * 64;
    const size_t bn = (size_t)blockIdx.x * 256;
    const int KT = K / BKH;

    float acc[2][8][4];
#pragma unroll
    for (int mt = 0; mt < 2; mt++)
#pragma unroll
        for (int nt = 0; nt < 8; nt++)
#pragma unroll
            for (int i = 0; i < 4; i++) acc[mt][nt][i] = 0.f;

    load_stage(A, Wt, bm, bn, K, 0, Abuf[0], Bbuf[0], tid);
    asm volatile("cp.async.commit_group;" ::: "memory");

    for (int kt = 0; kt < KT; kt++) {
        const int c = kt & 1;
        __syncthreads();
        if (kt + 1 < KT) {
            load_stage(A, Wt, bm, bn, K, (kt + 1) * BKH, Abuf[c ^ 1], Bbuf[c ^ 1], tid);
            asm volatile("cp.async.commit_group;" ::: "memory");
            asm volatile("cp.async.wait_group 1;" ::: "memory");
        } else {
            asm volatile("cp.async.wait_group 0;" ::: "memory");
        }
        __syncthreads();

        const __half* As = Abuf[c];
        const __half* Bs = Bbuf[c];
#pragma unroll
        for (int kk = 0; kk < 4; kk++) {
            const int kb = kk * 16;

            uint32_t af[2][4];
#pragma unroll
            for (int mt = 0; mt < 2; mt++) {
                int row = wm + mt * 16 + (quad & 1) * 8 + r8;
                int col = kb + (quad >> 1) * 8;
                uint32_t addr = smem_u32(&As[row * SPITCH + col]);
                asm volatile(
                    "ldmatrix.sync.aligned.m8n8.x4.shared.b16 {%0,%1,%2,%3}, [%4];"
                    : "=r"(af[mt][0]), "=r"(af[mt][1]), "=r"(af[mt][2]), "=r"(af[mt][3])
                    : "r"(addr));
            }

            uint32_t bf[8][2];
#pragma unroll
            for (int p = 0; p < 4; p++) {
                int row = wn + p * 16 + (quad >> 1) * 8 + r8;
                int col = kb + (quad & 1) * 8;
                uint32_t addr = smem_u32(&Bs[row * SPITCH + col]);
                uint32_t t0, t1, t2, t3;
                asm volatile(
                    "ldmatrix.sync.aligned.m8n8.x4.shared.b16 {%0,%1,%2,%3}, [%4];"
                    : "=r"(t0), "=r"(t1), "=r"(t2), "=r"(t3)
                    : "r"(addr));
                bf[2 * p + 0][0] = t0; bf[2 * p + 0][1] = t1;
                bf[2 * p + 1][0] = t2; bf[2 * p + 1][1] = t3;
            }

#pragma unroll
            for (int mt = 0; mt < 2; mt++)
#pragma unroll
                for (int nt = 0; nt < 8; nt++) {
                    asm volatile(
                        "mma.sync.aligned.m16n8k16.row.col.f32.f16.f16.f32 "
                        "{%0,%1,%2,%3}, {%4,%5,%6,%7}, {%8,%9}, {%0,%1,%2,%3};"
                        : "+f"(acc[mt][nt][0]), "+f"(acc[mt][nt][1]),
                          "+f"(acc[mt][nt][2]), "+f"(acc[mt][nt][3])
                        : "r"(af[mt][0]), "r"(af[mt][1]), "r"(af[mt][2]), "r"(af[mt][3]),
                          "r"(bf[nt][0]), "r"(bf[nt][1]));
                }
        }
    }

    // -------------------- Epilogue --------------------
#pragma unroll
    for (int mt = 0; mt < 2; mt++) {
#pragma unroll
        for (int nt = 0; nt < 8; nt++) {
            int cloc = wn + nt * 8 + tig * 2;
            float b0 = 0.f, b1 = 0.f;
            if (bias) { b0 = bias[bn + cloc]; b1 = bias[bn + cloc + 1]; }
            acc[mt][nt][0] += b0; acc[mt][nt][1] += b1;
            acc[mt][nt][2] += b0; acc[mt][nt][3] += b1;
            if (resid) {
                size_t row0 = bm + wm + mt * 16 + g;
                float2 r01 = *(const float2*)&resid[row0 * 256 + cloc];
                float2 r23 = *(const float2*)&resid[(row0 + 8) * 256 + cloc];
                acc[mt][nt][0] += r01.x; acc[mt][nt][1] += r01.y;
                acc[mt][nt][2] += r23.x; acc[mt][nt][3] += r23.y;
            }
            if (act == 1) {
#pragma unroll
                for (int i = 0; i < 4; i++) {
                    float v = acc[mt][nt][i];
                    acc[mt][nt][i] = v / (1.f + expf(-v));
                }
            }
        }
    }

    float rmean[2][2], rinv[2][2];
    if (ln) {
        // Stage 1: each n-warp-group owns a disjoint 64-column slice (wg);
        // warps in the same wg differ in wm -> disjoint rows. No atomics.
#pragma unroll
        for (int mt = 0; mt < 2; mt++) {
            float p0 = 0.f, q0 = 0.f, p1 = 0.f, q1 = 0.f;
#pragma unroll
            for (int nt = 0; nt < 8; nt++) {
                p0 += acc[mt][nt][0] + acc[mt][nt][1];
                q0 += acc[mt][nt][0] * acc[mt][nt][0] + acc[mt][nt][1] * acc[mt][nt][1];
                p1 += acc[mt][nt][2] + acc[mt][nt][3];
                q1 += acc[mt][nt][2] * acc[mt][nt][2] + acc[mt][nt][3] * acc[mt][nt][3];
            }
#pragma unroll
            for (int o = 1; o <= 2; o <<= 1) {
                p0 += __shfl_xor_sync(0xffffffffu, p0, o);
                q0 += __shfl_xor_sync(0xffffffffu, q0, o);
                p1 += __shfl_xor_sync(0xffffffffu, p1, o);
                q1 += __shfl_xor_sync(0xffffffffu, q1, o);
            }
            if (tig == 0) {
                int r0 = wm + mt * 16 + g;
                spart1[wg][r0] = p0;     spart2[wg][r0] = q0;
                spart1[wg][r0 + 8] = p1; spart2[wg][r0 + 8] = q1;
            }
        }
        __syncthreads();

        // Stage 2: 64 threads fold the 4 slice-partials per row.
        if (tid < 64) {
            float s = 0.f, s2 = 0.f;
#pragma unroll
            for (int w = 0; w < 4; w++) { s += spart1[w][tid]; s2 += spart2[w][tid]; }
            float m  = s * (1.f / 256.f);
            float vv = s2 * (1.f / 256.f) - m * m;
            smean[tid] = m;
            sinv[tid]  = rsqrtf(vv + 1e-5f);
        }
        __syncthreads();

#pragma unroll
        for (int mt = 0; mt < 2; mt++) {
            int r0 = wm + mt * 16 + g;
#pragma unroll
            for (int hh = 0; hh < 2; hh++) {
                rmean[mt][hh] = smean[r0 + hh * 8];
                rinv[mt][hh]  = sinv[r0 + hh * 8];
            }
        }
    }

    // Output target
    __half* chp = Ch;
    float*  cfp = Cf;
    int n_stride = N;
    size_t col_base = bn;
    if (qkv) {
        chp = Ch + (size_t)blockIdx.x * ((size_t)M_ROWS * E_DIM);
        n_stride = E_DIM;
        col_base = 0;
    }

#pragma unroll
    for (int mt = 0; mt < 2; mt++) {
#pragma unroll
        for (int nt = 0; nt < 8; nt++) {
            size_t row0 = bm + wm + mt * 16 + g;
            int    cloc = wn + nt * 8 + tig * 2;
            size_t col  = col_base + cloc;
            float v0 = acc[mt][nt][0], v1 = acc[mt][nt][1];
            float v2 = acc[mt][nt][2], v3 = acc[mt][nt][3];
            if (ln) {
                float ga0 = gamma[cloc], ga1 = gamma[cloc + 1];
                float be0 = beta[cloc],  be1 = beta[cloc + 1];
                v0 = (v0 - rmean[mt][0]) * rinv[mt][0] * ga0 + be0;
                v1 = (v1 - rmean[mt][0]) * rinv[mt][0] * ga1 + be1;
                v2 = (v2 - rmean[mt][1]) * rinv[mt][1] * ga0 + be0;
                v3 = (v3 - rmean[mt][1]) * rinv[mt][1] * ga1 + be1;
            }
            if (cfp) {
                float2 o01 = { v0, v1 };
                float2 o23 = { v2, v3 };
                *(float2*)&cfp[row0 * n_stride + col]       = o01;
                *(float2*)&cfp[(row0 + 8) * n_stride + col] = o23;
            }
            if (chp) {
                __half2 h01 = __floats2half2_rn(v0, v1);
                __half2 h23 = __floats2half2_rn(v2, v3);
                *(__half2*)&chp[row0 * n_stride + col]       = h01;
                *(__half2*)&chp[(row0 + 8) * n_stride + col] = h23;
            }
        }
    }
}

// ---------------------------------------------------------------------------
// Attention: per-token attention over NH=8 positions, H=8 heads, d=32.
// ---------------------------------------------------------------------------
__global__ __launch_bounds__(256)
void attn_kernel(const __half* __restrict__ qkv,
                 const float* __restrict__ pos1, const float* __restrict__ pos2,
                 const float* __restrict__ W_pos, const float* __restrict__ W_bias,
                 __half* __restrict__ out)
{
    const size_t QKV_OFF = (size_t)M_ROWS * E_DIM;
    const __half* q = qkv;
    const __half* k = qkv + QKV_OFF;
    const __half* v = qkv + 2 * QKV_OFF;

    int bn  = blockIdx.x;
    int tid = threadIdx.x;
    size_t base = (size_t)bn * NH * E_DIM;

    __shared__ __half sq[NH][E_DIM];
    __shared__ __half sk[NH][E_DIM];
    __shared__ __half sv[NH][E_DIM];
    __shared__ float  sbias[NH][H_HEADS];
    __shared__ float  satt[H_HEADS][NH][NH];

    {
        int r  = tid >> 5;
        int c8 = (tid & 31) * 8;
        *(uint4*)&sq[r][c8] = *(const uint4*)&q[base + (size_t)r * E_DIM + c8];
        *(uint4*)&sk[r][c8] = *(const uint4*)&k[base + (size_t)r * E_DIM + c8];
        *(uint4*)&sv[r][c8] = *(const uint4*)&v[base + (size_t)r * E_DIM + c8];
    }

    if (tid < NH * H_HEADS) {
        int nh = tid >> 3;
        int h  = tid & 7;
        size_t pbase = ((size_t)bn * NH + nh) * 2;
        float p0 = pos1[pbase + 0], p1 = pos1[pbase + 1];
        float p2 = pos2[pbase + 0], p3 = pos2[pbase + 1];
        float acc = 0.f;
#pragma unroll
        for (int pe = 0; pe < 32; pe++) {
            float e = p0 * W_pos[0 * 32 + pe] + p1 * W_pos[1 * 32 + pe]
                    + p2 * W_pos[2 * 32 + pe] + p3 * W_pos[3 * 32 + pe];
            e = e / (1.f + expf(-e));
            acc += e * W_bias[pe * H_HEADS + h];
        }
        sbias[nh][h] = acc;
    }
    __syncthreads();

    const float scale = 0.17677669529663687f;  // 1/sqrt(32)
#pragma unroll
    for (int it = 0; it < 2; it++) {
        int idx = tid + it * 256;
        int h  = idx >> 6;
        int qi = (idx >> 3) & 7;
        int ki = idx & 7;
        const __half2* qp = (const __half2*)&sq[qi][h * D_HEAD];
        const __half2* kp = (const __half2*)&sk[ki][h * D_HEAD];
        float s = 0.f;
#pragma unroll
        for (int j = 0; j < 16; j++) {
            float2 aq = __half22float2(qp[j]);
            float2 ak = __half22float2(kp[j]);
            s += aq.x * ak.x + aq.y * ak.y;
        }
        satt[h][qi][ki] = s * scale + sbias[ki][h];
    }
    __syncthreads();

    if (tid < H_HEADS * NH) {
        int h  = tid >> 3;
        int qi = tid & 7;
        float mx = satt[h][qi][0];
#pragma unroll
        for (int ki = 1; ki < NH; ki++) mx = fmaxf(mx, satt[h][qi][ki]);
        float sum = 0.f;
        float ex[NH];
#pragma unroll
        for (int ki = 0; ki < NH; ki++) { ex[ki] = expf(satt[h][qi][ki] - mx); sum += ex[ki]; }
        float rs = 1.f / sum;
#pragma unroll
        for (int ki = 0; ki < NH; ki++) satt[h][qi][ki] = ex[ki] * rs;
    }
    __syncthreads();

#pragma unroll
    for (int it = 0; it < 4; it++) {
        int idx = it * 256 + tid;
        int qi  = idx >> 7;
        int c2  = idx & 127;
        int h   = c2 >> 4;
        float2 o = { 0.f, 0.f };
        const float* att = &satt[h][qi][0];
#pragma unroll
        for (int ki = 0; ki < NH; ki++) {
            float2 vv = __half22float2(((const __half2*)&sv[ki][0])[c2]);
            o.x += att[ki] * vv.x;
            o.y += att[ki] * vv.y;
        }
        *(__half2*)&out[base + (size_t)qi * E_DIM + c2 * 2] = __floats2half2_rn(o.x, o.y);
    }
}

// ---------------------------------------------------------------------------
// Host launcher
// ---------------------------------------------------------------------------
extern "C" void kernel_launch(void* const* d_in, const int* in_sizes, int n_in,
                              void* d_out, int out_size)
{
    const float* x     = (const float*)d_in[0];
    const float* pos1  = (const float*)d_in[1];
    const float* pos2  = (const float*)d_in[2];
    const float* W_in  = (const float*)d_in[3];
    const float* gin   = (const float*)d_in[4];
    const float* bin   = (const float*)d_in[5];
    const float* Wq    = (const float*)d_in[6];
    const float* bq    = (const float*)d_in[7];
    const float* Wk    = (const float*)d_in[8];
    const float* bk    = (const float*)d_in[9];
    const float* Wv    = (const float*)d_in[10];
    const float* bv    = (const float*)d_in[11];
    const float* Wo    = (const float*)d_in[12];
    const float* bo    = (const float*)d_in[13];
    const float* W_pos = (const float*)d_in[14];
    const float* W_bias= (const float*)d_in[15];
    const float* W_ff1 = (const float*)d_in[16];
    const float* W_ff2 = (const float*)d_in[17];
    const float* g1    = (const float*)d_in[18];
    const float* b1    = (const float*)d_in[19];
    const float* g2    = (const float*)d_in[20];
    const float* b2    = (const float*)d_in[21];

    __half *hx, *ht, *hqkv, *ha, *hh1, *hff;
    float  *ft, *fh1, *bqkv;
    __half *wt_in, *wt_qkv, *wt_o, *wt_f1, *wt_f2;
    cudaGetSymbolAddress((void**)&hx,   g_hx);
    cudaGetSymbolAddress((void**)&ht,   g_ht);
    cudaGetSymbolAddress((void**)&hqkv, g_hqkv);
    cudaGetSymbolAddress((void**)&ha,   g_ha);
    cudaGetSymbolAddress((void**)&hh1,  g_hh1);
    cudaGetSymbolAddress((void**)&hff,  g_hff);
    cudaGetSymbolAddress((void**)&ft,   g_ft);
    cudaGetSymbolAddress((void**)&fh1,  g_fh1);
    cudaGetSymbolAddress((void**)&bqkv,  g_bqkv);
    cudaGetSymbolAddress((void**)&wt_in, g_wt_in);
    cudaGetSymbolAddress((void**)&wt_qkv,g_wt_qkv);
    cudaGetSymbolAddress((void**)&wt_o,  g_wt_o);
    cudaGetSymbolAddress((void**)&wt_f1, g_wt_f1);
    cudaGetSymbolAddress((void**)&wt_f2, g_wt_f2);

    cudaFuncSetAttribute(gemm_h, cudaFuncAttributeMaxDynamicSharedMemorySize, GEMM_SMEM);

    int nEE = E_DIM * E_DIM, nEF = E_DIM * FF_DIM;
    transpose_kernel<<<(nEE + 255) / 256, 256>>>(W_in,  wt_in,            E_DIM, E_DIM);
    transpose_kernel<<<(nEE + 255) / 256, 256>>>(Wq,    wt_qkv,           E_DIM, E_DIM);
    transpose_kernel<<<(nEE + 255) / 256, 256>>>(Wk,    wt_qkv + 1 * nEE, E_DIM, E_DIM);
    transpose_kernel<<<(nEE + 255) / 256, 256>>>(Wv,    wt_qkv + 2 * nEE, E_DIM, E_DIM);
    transpose_kernel<<<(nEE + 255) / 256, 256>>>(Wo,    wt_o,             E_DIM, E_DIM);
    transpose_kernel<<<(nEF + 255) / 256, 256>>>(W_ff1, wt_f1,            E_DIM, FF_DIM);
    transpose_kernel<<<(nEF + 255) / 256, 256>>>(W_ff2, wt_f2,            FF_DIM, E_DIM);
    concat_bias_kernel<<<3, 256>>>(bq, bk, bv, bqkv);

    size_t x8 = (size_t)M_ROWS * E_DIM / 8;
    conv_kernel<<<(unsigned)((x8 + 255) / 256), 256>>>(x, hx, x8);

    dim3 blk(256);
    dim3 gE  (1, M_ROWS / 64);     // (1, 2048), N=256
    dim3 gQKV(3, M_ROWS / 64);     // (3, 2048), N=768
    dim3 gFF (4, M_ROWS / 64);     // (4, 2048), N=1024

    // 1. t = LN(x @ W_in) -> ht (fp16) + ft (fp32)     [fused LN]
    gemm_h<<<gE, blk, GEMM_SMEM>>>(hx, wt_in, nullptr, nullptr, gin, bin,
                                   ht, ft, E_DIM, E_DIM, 0, 0, 1);

    // 2. fused q|k|v projection -> hqkv
    gemm_h<<<gQKV, blk, GEMM_SMEM>>>(ht, wt_qkv, bqkv, nullptr, nullptr, nullptr,
                                     hqkv, nullptr, E_DIM, 3 * E_DIM, 0, 1, 0);

    // 3. attention (+positional bias) -> ha
    attn_kernel<<<BN_TOK, 256>>>(hqkv, pos1, pos2, W_pos, W_bias, ha);

    // 4+5. h1 = LN(t + attn@Wo + bo) -> hh1 (fp16) + fh1 (fp32)   [fused]
    gemm_h<<<gE, blk, GEMM_SMEM>>>(ha, wt_o, bo, ft, g1, b1,
                                   hh1, fh1, E_DIM, E_DIM, 0, 0, 1);

    // 6. ff = silu(h1 @ W_ff1) -> hff
    gemm_h<<<gFF, blk, GEMM_SMEM>>>(hh1, wt_f1, nullptr, nullptr, nullptr, nullptr,
                                    hff, nullptr, E_DIM, FF_DIM, 1, 0, 0);

    // 7+8. out = LN(h1 + ff @ W_ff2) -> d_out (fp32)   [fused]
    gemm_h<<<gE, blk, GEMM_SMEM>>>(hff, wt_f2, nullptr, fh1, g2, b2,
                                   nullptr, (float*)d_out, FF_DIM, E_DIM, 0, 0, 1);
}